// round 4
// baseline (speedup 1.0000x reference)
#include <cuda_runtime.h>
#include <math.h>

#define MUL0 16
#define MUL1 8
#define DIM_F 40
#define NRB 16
#define NRD 64
#define W_NUMEL 576

#define THREADS 448
#define WARPS 14
#define E_TILE 8
#define GRID 148

struct __align__(16) WarpScratch {
    float h[NRD][E_TILE];     // 2048 B  post-silu, includes /8
    float x[E_TILE][DIM_F];   // 1280 B
    float emb[E_TILE][NRB];   // 512 B
    float dotv[E_TILE][MUL1]; // 256 B  includes 1/sqrt(3)
    float sh1[E_TILE][4];     // 128 B  sqrt(3)*unit
    float rr[E_TILE];         // 32 B
    int   src[E_TILE];        // 32 B
    int   dst[E_TILE];        // 32 B
    float pad[8];             // 32 B -> 4352 B total
};

#define W2_FLOATS (NRD * W_NUMEL)   // 36864
#define W1_FLOATS (NRB * NRD)       // 1024
#define SMEM_BYTES ((W2_FLOATS + W1_FLOATS) * 4 + WARPS * (int)sizeof(WarpScratch))

__device__ __forceinline__ float silu_scaled(float z) {
    // returns silu(z*0.25)/8, via tanh.approx: silu(a) = a*0.5*(1+tanh(a/2))
    float a = z * 0.25f;
    float th;
    asm("tanh.approx.f32 %0, %1;" : "=f"(th) : "f"(a * 0.5f));
    return a * (1.0f + th) * 0.0625f;   // 0.5 * 0.125
}

__global__ void zero_kernel(float4* __restrict__ out, int n4) {
    int i = blockIdx.x * blockDim.x + threadIdx.x;
    if (i < n4) out[i] = make_float4(0.f, 0.f, 0.f, 0.f);
}

__global__ __launch_bounds__(THREADS, 1)
void conv_kernel(const float* __restrict__ pos,
                 const float* __restrict__ f_in,
                 const int*   __restrict__ edge_src,
                 const int*   __restrict__ edge_dst,
                 const float* __restrict__ W1,
                 const float* __restrict__ W2,
                 float* __restrict__ f_out,
                 int n_edges)
{
    extern __shared__ float smem[];
    float* W2s = smem;
    float* W1s = smem + W2_FLOATS;
    WarpScratch* wsArr = reinterpret_cast<WarpScratch*>(smem + W2_FLOATS + W1_FLOATS);

    const int tid  = threadIdx.x;
    const int warp = tid >> 5;
    const int lane = tid & 31;
    WarpScratch* ws = &wsArr[warp];

    // ---- Stage weights once per block ----
    {
        const float4* src4 = reinterpret_cast<const float4*>(W2);
        float4* dst4 = reinterpret_cast<float4*>(W2s);
        for (int i = tid; i < W2_FLOATS / 4; i += THREADS) dst4[i] = src4[i];
        for (int i = tid; i < W1_FLOATS; i += THREADS) W1s[i] = W1[i];
    }
    __syncthreads();

    const int n_groups = (n_edges + E_TILE - 1) / E_TILE;
    const int gw = blockIdx.x * WARPS + warp;
    const int nw = gridDim.x * WARPS;

    for (int g = gw; g < n_groups; g += nw) {
        __syncwarp();
        // ---- Phase A: geometry (lanes 0..7) ----
        if (lane < E_TILE) {
            int e = g * E_TILE + lane;
            if (e < n_edges) {
                int es = edge_src[e], ed = edge_dst[e];
                float ax = pos[es * 3 + 0], ay = pos[es * 3 + 1], az = pos[es * 3 + 2];
                float bx = pos[ed * 3 + 0], by = pos[ed * 3 + 1], bz = pos[ed * 3 + 2];
                float dx = bx - ax, dy = by - ay, dz = bz - az;
                float r = sqrtf(dx * dx + dy * dy + dz * dz + 1e-12f);
                float inv = 1.7320508075688772f / r;   // sqrt(3)/r
                ws->src[lane] = es;
                ws->dst[lane] = ed;
                ws->rr[lane]  = r;
                ws->sh1[lane][0] = dx * inv;
                ws->sh1[lane][1] = dy * inv;
                ws->sh1[lane][2] = dz * inv;
            } else {
                ws->src[lane] = 0; ws->dst[lane] = 0;
                ws->rr[lane] = 1e9f;
                ws->sh1[lane][0] = 0.f; ws->sh1[lane][1] = 0.f; ws->sh1[lane][2] = 0.f;
            }
        }
        __syncwarp();
        // ---- Phase B: radial embedding + x gather ----
        #pragma unroll
        for (int t = 0; t < 4; t++) {               // 128 items: e x i
            int idx = lane + 32 * t;
            int e = idx >> 4, i = idx & 15;
            float v = (5.0f / 17.0f) * (float)(i + 1);
            float d = (ws->rr[e] - v) * 3.4f;       // 17/5
            float y = 0.0f;
            float d2 = d * d;
            if (d2 < 1.0f) {
                // 4.56544 * exp(2 - 2/(1-d^2))
                y = 4.56544f * __expf(2.0f - __fdividef(2.0f, 1.0f - d2));
            }
            ws->emb[e][i] = y;
        }
        #pragma unroll
        for (int t = 0; t < 10; t++) {              // 320 items: x gather
            int idx = lane + 32 * t;
            int e = idx / DIM_F, c = idx - e * DIM_F;
            ws->x[e][c] = f_in[ws->src[e] * DIM_F + c];
        }
        __syncwarp();
        // ---- Phase C: h = silu(emb@W1/4)/8 ; dotv ----
        #pragma unroll
        for (int p = 0; p < 2; p++) {
            int d = lane + 32 * p;
            float w1c[NRB];
            #pragma unroll
            for (int i = 0; i < NRB; i++) w1c[i] = W1s[i * NRD + d];
            float hz[E_TILE];
            #pragma unroll
            for (int e = 0; e < E_TILE; e++) {
                float z = 0.0f;
                #pragma unroll
                for (int i = 0; i < NRB; i++) z += ws->emb[e][i] * w1c[i];
                hz[e] = silu_scaled(z);
            }
            float4 hA = make_float4(hz[0], hz[1], hz[2], hz[3]);
            float4 hB = make_float4(hz[4], hz[5], hz[6], hz[7]);
            *reinterpret_cast<float4*>(&ws->h[d][0]) = hA;
            *reinterpret_cast<float4*>(&ws->h[d][4]) = hB;
        }
        #pragma unroll
        for (int t = 0; t < 2; t++) {               // dotv: 64 items
            int idx = lane + 32 * t;
            int e = idx >> 3, u = idx & 7;
            float dv = ws->x[e][16 + u * 3 + 0] * ws->sh1[e][0]
                     + ws->x[e][16 + u * 3 + 1] * ws->sh1[e][1]
                     + ws->x[e][16 + u * 3 + 2] * ws->sh1[e][2];
            ws->dotv[e][u] = dv * 0.57735026918962576f;  // 1/sqrt(3)
        }
        __syncwarp();

        // ---- Phase D: GEMV (3 passes of 6 columns) + register TP ----
        float po0[E_TILE], cf[E_TILE], t0a[E_TILE], t1a[E_TILE], t2a[E_TILE];
        #pragma unroll
        for (int e = 0; e < E_TILE; e++) {
            po0[e] = 0.f; cf[e] = 0.f; t0a[e] = 0.f; t1a[e] = 0.f; t2a[e] = 0.f;
        }

        #pragma unroll
        for (int pass = 0; pass < 3; pass++) {
            const int jb = pass * 6;
            unsigned long long acc[6][4];
            #pragma unroll
            for (int j6 = 0; j6 < 6; j6++)
                #pragma unroll
                for (int p = 0; p < 4; p++) acc[j6][p] = 0ULL;

            const float* wbase = W2s + jb * 32 + lane;
            #pragma unroll 2
            for (int d = 0; d < NRD; d++) {
                const ulonglong2* hp = reinterpret_cast<const ulonglong2*>(ws->h[d]);
                ulonglong2 h01 = hp[0];
                ulonglong2 h45 = hp[1];
                const float* row = wbase + d * W_NUMEL;
                #pragma unroll
                for (int j6 = 0; j6 < 6; j6++) {
                    float wv = row[j6 * 32];
                    unsigned long long wp;
                    asm("mov.b64 %0, {%1, %1};" : "=l"(wp) : "f"(wv));
                    asm("fma.rn.f32x2 %0, %1, %2, %0;" : "+l"(acc[j6][0]) : "l"(h01.x), "l"(wp));
                    asm("fma.rn.f32x2 %0, %1, %2, %0;" : "+l"(acc[j6][1]) : "l"(h01.y), "l"(wp));
                    asm("fma.rn.f32x2 %0, %1, %2, %0;" : "+l"(acc[j6][2]) : "l"(h45.x), "l"(wp));
                    asm("fma.rn.f32x2 %0, %1, %2, %0;" : "+l"(acc[j6][3]) : "l"(h45.y), "l"(wp));
                }
            }
            // TP for the 6 columns of this pass (j compile-time)
            #pragma unroll
            for (int j6 = 0; j6 < 6; j6++) {
                const int j = jb + j6;
                float wvv[E_TILE];
                #pragma unroll
                for (int p = 0; p < 4; p++)
                    asm("mov.b64 {%0, %1}, %2;"
                        : "=f"(wvv[2*p]), "=f"(wvv[2*p+1]) : "l"(acc[j6][p]));
                if (j < 8) {                          // w00: u=2j+(lane>>4), v=lane&15
                    int u = 2 * j + (lane >> 4);
                    #pragma unroll
                    for (int e = 0; e < E_TILE; e++)
                        po0[e] = fmaf(wvv[e], ws->x[e][u], po0[e]);
                } else if (j < 12) {                  // w01: u=4(j-8)+(lane>>3)
                    int u = 4 * (j - 8) + (lane >> 3);
                    #pragma unroll
                    for (int e = 0; e < E_TILE; e++)
                        cf[e] = fmaf(wvv[e], ws->x[e][u], cf[e]);
                } else if (j < 14) {                  // w10: u=4(j-12)+(lane>>3)
                    int u = 4 * (j - 12) + (lane >> 3);
                    #pragma unroll
                    for (int e = 0; e < E_TILE; e++) {
                        t0a[e] = fmaf(wvv[e], ws->x[e][16 + u * 3 + 0], t0a[e]);
                        t1a[e] = fmaf(wvv[e], ws->x[e][16 + u * 3 + 1], t1a[e]);
                        t2a[e] = fmaf(wvv[e], ws->x[e][16 + u * 3 + 2], t2a[e]);
                    }
                } else {                              // w11: u=2(j-14)+(lane>>4)
                    int u = 2 * (j - 14) + (lane >> 4);
                    #pragma unroll
                    for (int e = 0; e < E_TILE; e++)
                        po0[e] = fmaf(wvv[e], ws->dotv[e][u], po0[e]);
                }
            }
        }

        // ---- Phase E: shuffle reductions + global scatter ----
        {
            const float SCALE = 0.05103103630798288f;   // 1/(sqrt(24)*sqrt(16))
            #pragma unroll
            for (int e = 0; e < E_TILE; e++) {
                float o0 = po0[e] + __shfl_xor_sync(0xffffffffu, po0[e], 16);
                float c_ = cf[e];
                c_ += __shfl_xor_sync(0xffffffffu, c_, 8);
                c_ += __shfl_xor_sync(0xffffffffu, c_, 16);
                float a0 = t0a[e];
                a0 += __shfl_xor_sync(0xffffffffu, a0, 8);
                a0 += __shfl_xor_sync(0xffffffffu, a0, 16);
                float a1 = t1a[e];
                a1 += __shfl_xor_sync(0xffffffffu, a1, 8);
                a1 += __shfl_xor_sync(0xffffffffu, a1, 16);
                float a2 = t2a[e];
                a2 += __shfl_xor_sync(0xffffffffu, a2, 8);
                a2 += __shfl_xor_sync(0xffffffffu, a2, 16);
                int d_ = ws->dst[e];
                if (lane < 16)
                    atomicAdd(&f_out[d_ * DIM_F + lane], o0 * SCALE);
                if (lane < 8) {
                    float s0 = ws->sh1[e][0], s1 = ws->sh1[e][1], s2 = ws->sh1[e][2];
                    float* base = &f_out[d_ * DIM_F + 16 + 3 * lane];
                    atomicAdd(base + 0, (c_ * s0 + a0) * SCALE);
                    atomicAdd(base + 1, (c_ * s1 + a1) * SCALE);
                    atomicAdd(base + 2, (c_ * s2 + a2) * SCALE);
                }
            }
        }
    }
}

extern "C" void kernel_launch(void* const* d_in, const int* in_sizes, int n_in,
                              void* d_out, int out_size) {
    const float* pos  = (const float*)d_in[0];
    const float* f_in = (const float*)d_in[1];
    const int*   esrc = (const int*)d_in[2];
    const int*   edst = (const int*)d_in[3];
    const float* W1   = (const float*)d_in[4];
    const float* W2   = (const float*)d_in[5];
    float* out = (float*)d_out;
    int n_edges = in_sizes[2];

    cudaFuncSetAttribute(conv_kernel, cudaFuncAttributeMaxDynamicSharedMemorySize, SMEM_BYTES);

    int n4 = out_size / 4;
    zero_kernel<<<(n4 + 255) / 256, 256>>>((float4*)out, n4);
    conv_kernel<<<GRID, THREADS, SMEM_BYTES>>>(pos, f_in, esrc, edst, W1, W2, out, n_edges);
}

// round 6
// speedup vs baseline: 1.6062x; 1.6062x over previous
#include <cuda_runtime.h>
#include <cuda_bf16.h>
#include <cstdint>
#include <math.h>

#define MUL0 16
#define MUL1 8
#define DIM_F 40
#define NRB 16
#define NRD 64
#define W_NUMEL 576

#define THREADS 128
#define E_TILE 128
#define GRID 148

// ---- smem layout (bytes) ----
static constexpr int OFF_BHI = 0;                    // W2 hi: [576 n][64 k] bf16, 128B rows, XOR-swz
static constexpr int OFF_BLO = 73728;
static constexpr int OFF_AHI = 147456;               // h hi: [128 e][64 k] bf16, 128B rows, XOR-swz
static constexpr int OFF_ALO = 163840;
static constexpr int OFF_W1  = 180224;               // W1 f32 [16][64]
static constexpr int OFF_C   = 184320;               // C chunk [128][33] f32
static constexpr int OFF_X   = 201216;               // x_s [128][49] f32 (x0|x1|dot)
static constexpr int SMEM_TOTAL = 226304;
#define XPITCH 49

__device__ __forceinline__ unsigned short bf16b(float v) {
    __nv_bfloat16 b = __float2bfloat16_rn(v);
    return *reinterpret_cast<unsigned short*>(&b);
}
__device__ __forceinline__ float bf16f(unsigned short u) {
    __nv_bfloat16 b = *reinterpret_cast<__nv_bfloat16*>(&u);
    return __bfloat162float(b);
}
__device__ __forceinline__ float silu_scaled(float z) {   // silu(z/4)/8
    float a = z * 0.25f, th;
    asm("tanh.approx.f32 %0, %1;" : "=f"(th) : "f"(a * 0.5f));
    return a * (1.0f + th) * 0.0625f;
}
__device__ __forceinline__ void mma_bf16(float* d, const uint32_t* a, const uint32_t* b) {
    asm volatile("mma.sync.aligned.m16n8k16.row.col.f32.bf16.bf16.f32 "
        "{%0,%1,%2,%3}, {%4,%5,%6,%7}, {%8,%9}, {%0,%1,%2,%3};"
        : "+f"(d[0]), "+f"(d[1]), "+f"(d[2]), "+f"(d[3])
        : "r"(a[0]), "r"(a[1]), "r"(a[2]), "r"(a[3]), "r"(b[0]), "r"(b[1]));
}

__global__ void zero_kernel(float4* __restrict__ out, int n4) {
    int i = blockIdx.x * blockDim.x + threadIdx.x;
    if (i < n4) out[i] = make_float4(0.f, 0.f, 0.f, 0.f);
}

__global__ __launch_bounds__(THREADS, 1)
void conv_kernel(const float* __restrict__ pos,
                 const float* __restrict__ f_in,
                 const int*   __restrict__ edge_src,
                 const int*   __restrict__ edge_dst,
                 const float* __restrict__ W1,
                 const float* __restrict__ W2,
                 float* __restrict__ f_out,
                 int n_edges)
{
    extern __shared__ char smem[];
    const int tid  = threadIdx.x;
    const int warp = tid >> 5;
    const int lane = tid & 31;
    const int g    = lane >> 2;            // mma group id
    const int c4   = (lane & 3) << 2;      // byte offset of k-pair within 16B chunk

    float* W1s = reinterpret_cast<float*>(smem + OFF_W1);
    float* C_s = reinterpret_cast<float*>(smem + OFF_C);
    float* x_s = reinterpret_cast<float*>(smem + OFF_X);

    // ---- stage W2 hi/lo (once per block): [n][k] bf16, row=128B, 16B-chunk XOR row ----
    for (int idx = tid; idx < NRD * W_NUMEL; idx += THREADS) {
        int k = idx / W_NUMEL, n = idx - k * W_NUMEL;
        float w = W2[idx];
        unsigned short hb = bf16b(w);
        unsigned short lb = bf16b(w - bf16f(hb));
        int kb = k * 2;
        int boff = n * 128 + (kb & 15) + 16 * (((kb >> 4) ^ n) & 7);
        *reinterpret_cast<unsigned short*>(smem + OFF_BHI + boff) = hb;
        *reinterpret_cast<unsigned short*>(smem + OFF_BLO + boff) = lb;
    }
    for (int idx = tid; idx < NRB * NRD; idx += THREADS) W1s[idx] = W1[idx];
    __syncthreads();

    const int n_tiles = (n_edges + E_TILE - 1) / E_TILE;

    for (int tile = blockIdx.x; tile < n_tiles; tile += gridDim.x) {
        // ================= Phase 1: per-edge prep (thread = edge) =================
        const int e = tile * E_TILE + tid;
        const int valid = (e < n_edges);
        int my_dst = 0;
        float sh0 = 0.f, sh1 = 0.f, sh2 = 0.f;
        float r = 1e9f;
        {
            int es = 0;
            if (valid) {
                es = edge_src[e];
                my_dst = edge_dst[e];
                float ax = pos[es * 3 + 0], ay = pos[es * 3 + 1], az = pos[es * 3 + 2];
                float bx = pos[my_dst * 3 + 0], by = pos[my_dst * 3 + 1], bz = pos[my_dst * 3 + 2];
                float dx = bx - ax, dy = by - ay, dz = bz - az;
                r = sqrtf(dx * dx + dy * dy + dz * dz + 1e-12f);
                float inv = 1.7320508075688772f / r;      // sqrt(3)/r
                sh0 = dx * inv; sh1 = dy * inv; sh2 = dz * inv;
            }
            // gather x row (from node 0 if invalid; harmless)
            const float4* frow = reinterpret_cast<const float4*>(f_in + (size_t)es * DIM_F);
            float xr[DIM_F];
            #pragma unroll
            for (int q = 0; q < 10; q++) {
                float4 v = frow[q];
                xr[q * 4 + 0] = v.x; xr[q * 4 + 1] = v.y;
                xr[q * 4 + 2] = v.z; xr[q * 4 + 3] = v.w;
            }
            float* xs = x_s + tid * XPITCH;
            #pragma unroll
            for (int q = 0; q < DIM_F; q++) xs[q] = xr[q];
            #pragma unroll
            for (int u = 0; u < MUL1; u++) {
                float dv = xr[16 + u * 3 + 0] * sh0 + xr[16 + u * 3 + 1] * sh1
                         + xr[16 + u * 3 + 2] * sh2;
                xs[40 + u] = dv * 0.57735026918962576f;   // 1/sqrt(3)
            }
        }
        // radial embedding (registers)
        float emb[NRB];
        #pragma unroll
        for (int i = 0; i < NRB; i++) {
            float v = (5.0f / 17.0f) * (float)(i + 1);
            float d = (r - v) * 3.4f;
            float d2 = d * d;
            float y = 0.0f;
            if (d2 < 1.0f) y = 4.56544f * __expf(2.0f - __fdividef(2.0f, 1.0f - d2));
            emb[i] = y;
        }
        // h = silu(emb@W1/4)/8  -> A hi/lo rows (bf16, XOR-swz)
        #pragma unroll
        for (int d4 = 0; d4 < 16; d4++) {
            float z0 = 0.f, z1 = 0.f, z2 = 0.f, z3 = 0.f;
            #pragma unroll
            for (int i = 0; i < NRB; i++) {
                float4 wv = *reinterpret_cast<const float4*>(W1s + i * NRD + d4 * 4);
                z0 = fmaf(emb[i], wv.x, z0);
                z1 = fmaf(emb[i], wv.y, z1);
                z2 = fmaf(emb[i], wv.z, z2);
                z3 = fmaf(emb[i], wv.w, z3);
            }
            float h0 = silu_scaled(z0), h1 = silu_scaled(z1);
            float h2 = silu_scaled(z2), h3 = silu_scaled(z3);
            unsigned short h0b = bf16b(h0), h1b = bf16b(h1);
            unsigned short h2b = bf16b(h2), h3b = bf16b(h3);
            uint32_t hiA = (uint32_t)h0b | ((uint32_t)h1b << 16);
            uint32_t hiB = (uint32_t)h2b | ((uint32_t)h3b << 16);
            unsigned short l0 = bf16b(h0 - bf16f(h0b)), l1 = bf16b(h1 - bf16f(h1b));
            unsigned short l2 = bf16b(h2 - bf16f(h2b)), l3 = bf16b(h3 - bf16f(h3b));
            uint32_t loA = (uint32_t)l0 | ((uint32_t)l1 << 16);
            uint32_t loB = (uint32_t)l2 | ((uint32_t)l3 << 16);
            int kb = d4 * 8;                                 // byte offset of d pair base
            int off = tid * 128 + (kb & 15) + 16 * (((kb >> 4) ^ tid) & 7);
            *reinterpret_cast<uint32_t*>(smem + OFF_AHI + off)     = hiA;
            *reinterpret_cast<uint32_t*>(smem + OFF_AHI + off + 4) = hiB;
            *reinterpret_cast<uint32_t*>(smem + OFF_ALO + off)     = loA;
            *reinterpret_cast<uint32_t*>(smem + OFF_ALO + off + 4) = loB;
        }
        __syncthreads();

        // ================= Phase 2: GEMM chunks + consume =================
        float po0[16], cf[8], t0[8], t1[8], t2[8];
        #pragma unroll
        for (int i = 0; i < 16; i++) po0[i] = 0.f;
        #pragma unroll
        for (int i = 0; i < 8; i++) { cf[i] = 0.f; t0[i] = 0.f; t1[i] = 0.f; t2[i] = 0.f; }

        const int r0 = 32 * warp + g;                 // this thread's A rows: r0, +8, +16, +24

        for (int cc = 0; cc < 18; cc++) {
            const int nbase = cc * 32;
            float acc[2][4][4];
            #pragma unroll
            for (int mf = 0; mf < 2; mf++)
                #pragma unroll
                for (int nt = 0; nt < 4; nt++)
                    #pragma unroll
                    for (int q = 0; q < 4; q++) acc[mf][nt][q] = 0.f;

            #pragma unroll
            for (int ks = 0; ks < 4; ks++) {
                const int ch0 = 2 * ks, ch1 = 2 * ks + 1;
                uint32_t ahi[2][4], alo[2][4], bhi[4][2], blo[4][2];
                #pragma unroll
                for (int mf = 0; mf < 2; mf++) {
                    int ra = r0 + 16 * mf;            // ra and ra+8 share (row&7)
                    int sw0 = 16 * ((ch0 ^ ra) & 7), sw1 = 16 * ((ch1 ^ ra) & 7);
                    int oa = ra * 128 + c4, ob = oa + 8 * 128;
                    ahi[mf][0] = *reinterpret_cast<const uint32_t*>(smem + OFF_AHI + oa + sw0);
                    ahi[mf][1] = *reinterpret_cast<const uint32_t*>(smem + OFF_AHI + ob + sw0);
                    ahi[mf][2] = *reinterpret_cast<const uint32_t*>(smem + OFF_AHI + oa + sw1);
                    ahi[mf][3] = *reinterpret_cast<const uint32_t*>(smem + OFF_AHI + ob + sw1);
                    alo[mf][0] = *reinterpret_cast<const uint32_t*>(smem + OFF_ALO + oa + sw0);
                    alo[mf][1] = *reinterpret_cast<const uint32_t*>(smem + OFF_ALO + ob + sw0);
                    alo[mf][2] = *reinterpret_cast<const uint32_t*>(smem + OFF_ALO + oa + sw1);
                    alo[mf][3] = *reinterpret_cast<const uint32_t*>(smem + OFF_ALO + ob + sw1);
                }
                #pragma unroll
                for (int nt = 0; nt < 4; nt++) {
                    int rn = nbase + nt * 8 + g;
                    int on = rn * 128 + c4;
                    int s0 = 16 * ((ch0 ^ rn) & 7), s1 = 16 * ((ch1 ^ rn) & 7);
                    bhi[nt][0] = *reinterpret_cast<const uint32_t*>(smem + OFF_BHI + on + s0);
                    bhi[nt][1] = *reinterpret_cast<const uint32_t*>(smem + OFF_BHI + on + s1);
                    blo[nt][0] = *reinterpret_cast<const uint32_t*>(smem + OFF_BLO + on + s0);
                    blo[nt][1] = *reinterpret_cast<const uint32_t*>(smem + OFF_BLO + on + s1);
                }
                #pragma unroll
                for (int mf = 0; mf < 2; mf++)
                    #pragma unroll
                    for (int nt = 0; nt < 4; nt++) {
                        mma_bf16(acc[mf][nt], ahi[mf], bhi[nt]);
                        mma_bf16(acc[mf][nt], alo[mf], bhi[nt]);
                        mma_bf16(acc[mf][nt], ahi[mf], blo[nt]);
                    }
            }
            // store C chunk [128][33]
            #pragma unroll
            for (int mf = 0; mf < 2; mf++) {
                int ra = r0 + 16 * mf;
                #pragma unroll
                for (int nt = 0; nt < 4; nt++) {
                    int col = nt * 8 + ((lane & 3) << 1);
                    C_s[ra * 33 + col]           = acc[mf][nt][0];
                    C_s[ra * 33 + col + 1]       = acc[mf][nt][1];
                    C_s[(ra + 8) * 33 + col]     = acc[mf][nt][2];
                    C_s[(ra + 8) * 33 + col + 1] = acc[mf][nt][3];
                }
            }
            __syncthreads();

            // consume: thread = edge
            {
                float Cr[32];
                const float* crow = C_s + tid * 33;
                #pragma unroll
                for (int i = 0; i < 32; i++) Cr[i] = crow[i];
                const float* xs = x_s + tid * XPITCH;

                if (cc < 8) {                         // w00: u = 2cc + (i>>4), v = i&15
                    float xa = xs[2 * cc], xb = xs[2 * cc + 1];
                    #pragma unroll
                    for (int i = 0; i < 16; i++) po0[i] = fmaf(Cr[i], xa, po0[i]);
                    #pragma unroll
                    for (int i = 0; i < 16; i++) po0[i] = fmaf(Cr[16 + i], xb, po0[i]);
                } else if (cc < 12) {                 // w01: u = 4(cc-8)+(i>>3), wp = i&7
                    int ub = 4 * (cc - 8);
                    float xa = xs[ub], xb = xs[ub + 1], xc = xs[ub + 2], xd = xs[ub + 3];
                    #pragma unroll
                    for (int i = 0; i < 8; i++) cf[i] = fmaf(Cr[i], xa, cf[i]);
                    #pragma unroll
                    for (int i = 0; i < 8; i++) cf[i] = fmaf(Cr[8 + i], xb, cf[i]);
                    #pragma unroll
                    for (int i = 0; i < 8; i++) cf[i] = fmaf(Cr[16 + i], xc, cf[i]);
                    #pragma unroll
                    for (int i = 0; i < 8; i++) cf[i] = fmaf(Cr[24 + i], xd, cf[i]);
                } else if (cc < 14) {                 // w10: u = 4(cc-12)+(i>>3), wp = i&7
                    int ub = 4 * (cc - 12);
                    #pragma unroll
                    for (int q = 0; q < 4; q++) {
                        float a0 = xs[16 + (ub + q) * 3 + 0];
                        float a1 = xs[16 + (ub + q) * 3 + 1];
                        float a2 = xs[16 + (ub + q) * 3 + 2];
                        #pragma unroll
                        for (int i = 0; i < 8; i++) {
                            float w = Cr[8 * q + i];
                            t0[i] = fmaf(w, a0, t0[i]);
                            t1[i] = fmaf(w, a1, t1[i]);
                            t2[i] = fmaf(w, a2, t2[i]);
                        }
                    }
                } else {                              // w11: u = 2(cc-14)+(i>>4), v = i&15
                    float da = xs[40 + 2 * (cc - 14)], db = xs[40 + 2 * (cc - 14) + 1];
                    #pragma unroll
                    for (int i = 0; i < 16; i++) po0[i] = fmaf(Cr[i], da, po0[i]);
                    #pragma unroll
                    for (int i = 0; i < 16; i++) po0[i] = fmaf(Cr[16 + i], db, po0[i]);
                }
            }
            __syncthreads();
        }

        // ================= Phase 3: combine + scatter =================
        if (valid) {
            const float SCALE = 0.05103103630798288f;   // 1/(sqrt(24)*4)
            float o[DIM_F];
            #pragma unroll
            for (int v = 0; v < 16; v++) o[v] = po0[v] * SCALE;
            #pragma unroll
            for (int wp = 0; wp < 8; wp++) {
                o[16 + wp * 3 + 0] = (cf[wp] * sh0 + t0[wp]) * SCALE;
                o[16 + wp * 3 + 1] = (cf[wp] * sh1 + t1[wp]) * SCALE;
                o[16 + wp * 3 + 2] = (cf[wp] * sh2 + t2[wp]) * SCALE;
            }
            float* base = f_out + (size_t)my_dst * DIM_F;
            #pragma unroll
            for (int q = 0; q < 10; q++) {
                asm volatile("red.global.add.v4.f32 [%0], {%1, %2, %3, %4};"
                             :: "l"(base + q * 4),
                                "f"(o[q * 4 + 0]), "f"(o[q * 4 + 1]),
                                "f"(o[q * 4 + 2]), "f"(o[q * 4 + 3]) : "memory");
            }
        }
        __syncthreads();
    }
}

extern "C" void kernel_launch(void* const* d_in, const int* in_sizes, int n_in,
                              void* d_out, int out_size) {
    const float* pos  = (const float*)d_in[0];
    const float* f_in = (const float*)d_in[1];
    const int*   esrc = (const int*)d_in[2];
    const int*   edst = (const int*)d_in[3];
    const float* W1   = (const float*)d_in[4];
    const float* W2   = (const float*)d_in[5];
    float* out = (float*)d_out;
    int n_edges = in_sizes[2];

    cudaFuncSetAttribute(conv_kernel, cudaFuncAttributeMaxDynamicSharedMemorySize, SMEM_TOTAL);

    int n4 = out_size / 4;
    zero_kernel<<<(n4 + 255) / 256, 256>>>((float4*)out, n4);
    conv_kernel<<<GRID, THREADS, SMEM_TOTAL>>>(pos, f_in, esrc, edst, W1, W2, out, n_edges);
}

// round 7
// speedup vs baseline: 2.7756x; 1.7281x over previous
#include <cuda_runtime.h>
#include <cuda_fp16.h>
#include <cstdint>
#include <math.h>

#define MUL0 16
#define MUL1 8
#define DIM_F 40
#define NRB 16
#define NRD 64
#define W_NUMEL 576

#define THREADS 256
#define E_TILE 128
#define GRID 148
#define XP 53            // x_s row pitch (floats): 40 x | 8 dot | 3 sh | rr | dst

// ---- smem layout (bytes) ----
static constexpr int OFF_B   = 0;          // W2 hi fp16 [576 n][64 k], 128B rows, XOR-swz (73728)
static constexpr int OFF_AHI = 73728;      // h hi fp16 [128 e][64 k] swz (16384)
static constexpr int OFF_ALO = 90112;      // h lo fp16 (16384)
static constexpr int OFF_W1  = 106496;     // W1 f32 [16][64] (4096)
static constexpr int OFF_X   = 110592;     // x_s [128][53] f32 (27136)
static constexpr int OFF_MB  = 137728;     // merge buf [128][49] f32 (25088)
static constexpr int SMEM_TOTAL = 162816;

__device__ __forceinline__ float silu_scaled(float z) {   // silu(z/4)/8
    float a = z * 0.25f, th;
    asm("tanh.approx.f32 %0, %1;" : "=f"(th) : "f"(a * 0.5f));
    return a * (1.0f + th) * 0.0625f;
}
__device__ __forceinline__ void mma_f16(float* d, const uint32_t* a, const uint32_t* b) {
    asm volatile("mma.sync.aligned.m16n8k16.row.col.f32.f16.f16.f32 "
        "{%0,%1,%2,%3}, {%4,%5,%6,%7}, {%8,%9}, {%0,%1,%2,%3};"
        : "+f"(d[0]), "+f"(d[1]), "+f"(d[2]), "+f"(d[3])
        : "r"(a[0]), "r"(a[1]), "r"(a[2]), "r"(a[3]), "r"(b[0]), "r"(b[1]));
}

__global__ void zero_kernel(float4* __restrict__ out, int n4) {
    int i = blockIdx.x * blockDim.x + threadIdx.x;
    if (i < n4) out[i] = make_float4(0.f, 0.f, 0.f, 0.f);
}

__global__ __launch_bounds__(THREADS, 1)
void conv_kernel(const float* __restrict__ pos,
                 const float* __restrict__ f_in,
                 const int*   __restrict__ edge_src,
                 const int*   __restrict__ edge_dst,
                 const float* __restrict__ W1,
                 const float* __restrict__ W2,
                 float* __restrict__ f_out,
                 int n_edges)
{
    extern __shared__ char smem[];
    const int tid  = threadIdx.x;
    const int warp = tid >> 5;
    const int lane = tid & 31;
    const int g    = lane >> 2;       // mma octet id (row/col within 8)
    const int c    = lane & 3;        // k-pair / col-pair selector
    const int mi   = warp & 3;        // m-group: rows 32*mi .. 32*mi+31
    const int ni   = warp >> 2;       // n-half: cols 16*ni .. +15 of each chunk

    float* x_s  = reinterpret_cast<float*>(smem + OFF_X);
    float* mbuf = reinterpret_cast<float*>(smem + OFF_MB);
    float* W1s  = reinterpret_cast<float*>(smem + OFF_W1);

    // ---- stage W2 hi (fp16) and W1 once per block ----
    for (int idx = tid; idx < NRD * W_NUMEL; idx += THREADS) {
        int k = idx / W_NUMEL, n = idx - k * W_NUMEL;
        __half hb = __float2half_rn(W2[idx]);
        int kb = k * 2;
        int off = n * 128 + (kb & 15) + 16 * (((kb >> 4) ^ n) & 7);
        *reinterpret_cast<__half*>(smem + OFF_B + off) = hb;
    }
    for (int idx = tid; idx < NRB * NRD; idx += THREADS) W1s[idx] = W1[idx];
    __syncthreads();

    const int n_tiles = (n_edges + E_TILE - 1) / E_TILE;
    const int le0 = 32 * mi + g;                 // first local edge this thread owns

    for (int tile = blockIdx.x; tile < n_tiles; tile += gridDim.x) {
        // ============ Phase 1: geometry + x gather (thread = edge, tid<128) ============
        if (tid < E_TILE) {
            int e = tile * E_TILE + tid;
            float* xs = x_s + tid * XP;
            float r = 1e9f;
            float s0 = 0.f, s1 = 0.f, s2 = 0.f;
            int es = 0, ed = 0;
            if (e < n_edges) {
                es = edge_src[e]; ed = edge_dst[e];
                float ax = pos[es * 3 + 0], ay = pos[es * 3 + 1], az = pos[es * 3 + 2];
                float bx = pos[ed * 3 + 0], by = pos[ed * 3 + 1], bz = pos[ed * 3 + 2];
                float dx = bx - ax, dy = by - ay, dz = bz - az;
                r = sqrtf(dx * dx + dy * dy + dz * dz + 1e-12f);
                float inv = 1.7320508075688772f / r;       // sqrt(3)/r
                s0 = dx * inv; s1 = dy * inv; s2 = dz * inv;
            }
            const float4* frow = reinterpret_cast<const float4*>(f_in + (size_t)es * DIM_F);
            float xr[DIM_F];
            #pragma unroll
            for (int q = 0; q < 10; q++) {
                float4 v = frow[q];
                xr[q * 4 + 0] = v.x; xr[q * 4 + 1] = v.y;
                xr[q * 4 + 2] = v.z; xr[q * 4 + 3] = v.w;
            }
            #pragma unroll
            for (int q = 0; q < DIM_F; q++) xs[q] = xr[q];
            #pragma unroll
            for (int u = 0; u < MUL1; u++) {
                float dv = xr[16 + u * 3 + 0] * s0 + xr[16 + u * 3 + 1] * s1
                         + xr[16 + u * 3 + 2] * s2;
                xs[40 + u] = dv * 0.57735026918962576f;    // 1/sqrt(3)
            }
            xs[48] = s0; xs[49] = s1; xs[50] = s2;
            xs[51] = r;
            xs[52] = __int_as_float(ed);
        }
        __syncthreads();

        // ============ Phase 2: h = silu(emb@W1/4)/8 -> A hi/lo fp16 (2 thr/edge) ============
        {
            const int e = tid >> 1;
            const int half_ = tid & 1;
            float r = x_s[e * XP + 51];
            float emb[NRB];
            #pragma unroll
            for (int i = 0; i < NRB; i++) {
                float v = (5.0f / 17.0f) * (float)(i + 1);
                float d = (r - v) * 3.4f;
                float d2 = d * d;
                float y = 0.0f;
                if (d2 < 1.0f) y = 4.56544f * __expf(2.0f - __fdividef(2.0f, 1.0f - d2));
                emb[i] = y;
            }
            #pragma unroll
            for (int d4 = 0; d4 < 8; d4++) {
                float z0 = 0.f, z1 = 0.f, z2 = 0.f, z3 = 0.f;
                #pragma unroll
                for (int i = 0; i < NRB; i++) {
                    float4 wv = *reinterpret_cast<const float4*>(W1s + i * NRD + half_ * 32 + d4 * 4);
                    z0 = fmaf(emb[i], wv.x, z0);
                    z1 = fmaf(emb[i], wv.y, z1);
                    z2 = fmaf(emb[i], wv.z, z2);
                    z3 = fmaf(emb[i], wv.w, z3);
                }
                float h0 = silu_scaled(z0), h1 = silu_scaled(z1);
                float h2 = silu_scaled(z2), h3 = silu_scaled(z3);
                // two fp16 pairs: d = half*32 + d4*4 + {0,1} and {2,3}
                #pragma unroll
                for (int p = 0; p < 2; p++) {
                    float ha = p ? h2 : h0, hb_ = p ? h3 : h1;
                    __half hahi = __float2half_rn(ha), hbhi = __float2half_rn(hb_);
                    __half halo = __float2half_rn(ha - __half2float(hahi));
                    __half hblo = __float2half_rn(hb_ - __half2float(hbhi));
                    uint32_t hip = (uint32_t)*reinterpret_cast<unsigned short*>(&hahi)
                                 | ((uint32_t)*reinterpret_cast<unsigned short*>(&hbhi) << 16);
                    uint32_t lop = (uint32_t)*reinterpret_cast<unsigned short*>(&halo)
                                 | ((uint32_t)*reinterpret_cast<unsigned short*>(&hblo) << 16);
                    int d = half_ * 32 + d4 * 4 + p * 2;
                    int kb = d * 2;
                    int off = e * 128 + (kb & 15) + 16 * (((kb >> 4) ^ e) & 7);
                    *reinterpret_cast<uint32_t*>(smem + OFF_AHI + off) = hip;
                    *reinterpret_cast<uint32_t*>(smem + OFF_ALO + off) = lop;
                }
            }
        }
        __syncthreads();

        // ============ Phase 3: load A fragments into registers (once per tile) ============
        uint32_t Ahi[2][4][4], Alo[2][4][4];
        #pragma unroll
        for (int mf = 0; mf < 2; mf++) {
            int ra = le0 + 16 * mf;               // ra&7 == g
            int oa = ra * 128 + 4 * c;
            int ob = oa + 1024;
            #pragma unroll
            for (int ks = 0; ks < 4; ks++) {
                int s0 = 16 * (((2 * ks) ^ ra) & 7);
                int s1 = 16 * (((2 * ks + 1) ^ ra) & 7);
                Ahi[mf][ks][0] = *reinterpret_cast<const uint32_t*>(smem + OFF_AHI + oa + s0);
                Ahi[mf][ks][1] = *reinterpret_cast<const uint32_t*>(smem + OFF_AHI + ob + s0);
                Ahi[mf][ks][2] = *reinterpret_cast<const uint32_t*>(smem + OFF_AHI + oa + s1);
                Ahi[mf][ks][3] = *reinterpret_cast<const uint32_t*>(smem + OFF_AHI + ob + s1);
                Alo[mf][ks][0] = *reinterpret_cast<const uint32_t*>(smem + OFF_ALO + oa + s0);
                Alo[mf][ks][1] = *reinterpret_cast<const uint32_t*>(smem + OFF_ALO + ob + s0);
                Alo[mf][ks][2] = *reinterpret_cast<const uint32_t*>(smem + OFF_ALO + oa + s1);
                Alo[mf][ks][3] = *reinterpret_cast<const uint32_t*>(smem + OFF_ALO + ob + s1);
            }
        }

        // per-edge TP partials: 4 edges (le0, +8, +16, +24)
        float po0p[4][4], cfp[4][2], tpp[4][2][3];
        #pragma unroll
        for (int j = 0; j < 4; j++) {
            #pragma unroll
            for (int s = 0; s < 4; s++) po0p[j][s] = 0.f;
            cfp[j][0] = 0.f; cfp[j][1] = 0.f;
            #pragma unroll
            for (int b = 0; b < 2; b++)
                #pragma unroll
                for (int k = 0; k < 3; k++) tpp[j][b][k] = 0.f;
        }

        // ============ Phase 4: 18 GEMM chunks, consumed in-register ============
        for (int cc = 0; cc < 18; cc++) {
            float acc[2][2][4];
            #pragma unroll
            for (int mf = 0; mf < 2; mf++)
                #pragma unroll
                for (int nt = 0; nt < 2; nt++)
                    #pragma unroll
                    for (int q = 0; q < 4; q++) acc[mf][nt][q] = 0.f;

            #pragma unroll
            for (int ks = 0; ks < 4; ks++) {
                uint32_t bh[2][2];
                #pragma unroll
                for (int nt = 0; nt < 2; nt++) {
                    int n = cc * 32 + ni * 16 + nt * 8 + g;   // n&7 == g
                    int on = n * 128 + 4 * c;
                    bh[nt][0] = *reinterpret_cast<const uint32_t*>(
                        smem + OFF_B + on + 16 * (((2 * ks) ^ n) & 7));
                    bh[nt][1] = *reinterpret_cast<const uint32_t*>(
                        smem + OFF_B + on + 16 * (((2 * ks + 1) ^ n) & 7));
                }
                #pragma unroll
                for (int mf = 0; mf < 2; mf++)
                    #pragma unroll
                    for (int nt = 0; nt < 2; nt++) {
                        mma_f16(acc[mf][nt], Ahi[mf][ks], bh[nt]);
                        mma_f16(acc[mf][nt], Alo[mf][ks], bh[nt]);
                    }
            }

            // ---- consume: row = edge, col = 32cc + 16ni + 8nt + 2c + (q&1) ----
            if (cc < 8) {                          // w00: u = 2cc+ni (uniform)
                int u = 2 * cc + ni;
                float xv[4];
                #pragma unroll
                for (int j = 0; j < 4; j++) xv[j] = x_s[(le0 + 8 * j) * XP + u];
                #pragma unroll
                for (int mf = 0; mf < 2; mf++)
                    #pragma unroll
                    for (int nt = 0; nt < 2; nt++)
                        #pragma unroll
                        for (int q = 0; q < 4; q++) {
                            int j = 2 * mf + (q >> 1);
                            po0p[j][2 * nt + (q & 1)] =
                                fmaf(acc[mf][nt][q], xv[j], po0p[j][2 * nt + (q & 1)]);
                        }
            } else if (cc < 12) {                  // w01: u = 4(cc-8)+2ni+nt
                int ub = 4 * (cc - 8) + 2 * ni;
                float xv[4][2];
                #pragma unroll
                for (int j = 0; j < 4; j++) {
                    xv[j][0] = x_s[(le0 + 8 * j) * XP + ub];
                    xv[j][1] = x_s[(le0 + 8 * j) * XP + ub + 1];
                }
                #pragma unroll
                for (int mf = 0; mf < 2; mf++)
                    #pragma unroll
                    for (int nt = 0; nt < 2; nt++)
                        #pragma unroll
                        for (int q = 0; q < 4; q++) {
                            int j = 2 * mf + (q >> 1);
                            cfp[j][q & 1] = fmaf(acc[mf][nt][q], xv[j][nt], cfp[j][q & 1]);
                        }
            } else if (cc < 14) {                  // w10: u = 4(cc-12)+2ni+nt
                int ub = 4 * (cc - 12) + 2 * ni;
                float xv[4][2][3];
                #pragma unroll
                for (int j = 0; j < 4; j++)
                    #pragma unroll
                    for (int nt = 0; nt < 2; nt++)
                        #pragma unroll
                        for (int k = 0; k < 3; k++)
                            xv[j][nt][k] = x_s[(le0 + 8 * j) * XP + 16 + 3 * (ub + nt) + k];
                #pragma unroll
                for (int mf = 0; mf < 2; mf++)
                    #pragma unroll
                    for (int nt = 0; nt < 2; nt++)
                        #pragma unroll
                        for (int q = 0; q < 4; q++) {
                            int j = 2 * mf + (q >> 1);
                            #pragma unroll
                            for (int k = 0; k < 3; k++)
                                tpp[j][q & 1][k] =
                                    fmaf(acc[mf][nt][q], xv[j][nt][k], tpp[j][q & 1][k]);
                        }
            } else {                               // w11: u = 2(cc-14)+ni
                int u = 2 * (cc - 14) + ni;
                float dv[4];
                #pragma unroll
                for (int j = 0; j < 4; j++) dv[j] = x_s[(le0 + 8 * j) * XP + 40 + u];
                #pragma unroll
                for (int mf = 0; mf < 2; mf++)
                    #pragma unroll
                    for (int nt = 0; nt < 2; nt++)
                        #pragma unroll
                        for (int q = 0; q < 4; q++) {
                            int j = 2 * mf + (q >> 1);
                            po0p[j][2 * nt + (q & 1)] =
                                fmaf(acc[mf][nt][q], dv[j], po0p[j][2 * nt + (q & 1)]);
                        }
            }
        }

        // ============ Phase 5: ni-merge + scatter ============
        if (ni == 1) {
            #pragma unroll
            for (int j = 0; j < 4; j++) {
                float* mb = mbuf + (le0 + 8 * j) * 49 + c * 12;
                mb[0] = po0p[j][0]; mb[1] = po0p[j][1];
                mb[2] = po0p[j][2]; mb[3] = po0p[j][3];
                mb[4] = cfp[j][0];  mb[5] = cfp[j][1];
                #pragma unroll
                for (int b = 0; b < 2; b++)
                    #pragma unroll
                    for (int k = 0; k < 3; k++) mb[6 + 3 * b + k] = tpp[j][b][k];
            }
        }
        __syncthreads();
        if (ni == 0) {
            const float SC = 0.05103103630798288f;   // 1/(sqrt(24)*4)
            #pragma unroll
            for (int j = 0; j < 4; j++) {
                int le = le0 + 8 * j;
                const float* mb = mbuf + le * 49 + c * 12;
                float p0 = po0p[j][0] + mb[0], p1 = po0p[j][1] + mb[1];
                float p2 = po0p[j][2] + mb[2], p3 = po0p[j][3] + mb[3];
                float cf0 = cfp[j][0] + mb[4], cf1 = cfp[j][1] + mb[5];
                float ta[2][3];
                #pragma unroll
                for (int b = 0; b < 2; b++)
                    #pragma unroll
                    for (int k = 0; k < 3; k++) ta[b][k] = tpp[j][b][k] + mb[6 + 3 * b + k];

                if (tile * E_TILE + le < n_edges) {
                    const float* xs = x_s + le * XP;
                    float s0 = xs[48], s1 = xs[49], s2 = xs[50];
                    int dst = __float_as_int(xs[52]);
                    float* base = f_out + (size_t)dst * DIM_F;
                    // po0: v = {2c, 2c+1} and {8+2c, 8+2c+1}
                    asm volatile("red.global.add.v2.f32 [%0], {%1, %2};"
                                 :: "l"(base + 2 * c), "f"(p0 * SC), "f"(p1 * SC) : "memory");
                    asm volatile("red.global.add.v2.f32 [%0], {%1, %2};"
                                 :: "l"(base + 8 + 2 * c), "f"(p2 * SC), "f"(p3 * SC) : "memory");
                    // out1: wp = 2c, 2c+1 -> 6 consecutive floats at 16 + 6c
                    float o0 = (cf0 * s0 + ta[0][0]) * SC;
                    float o1 = (cf0 * s1 + ta[0][1]) * SC;
                    float o2 = (cf0 * s2 + ta[0][2]) * SC;
                    float o3 = (cf1 * s0 + ta[1][0]) * SC;
                    float o4 = (cf1 * s1 + ta[1][1]) * SC;
                    float o5 = (cf1 * s2 + ta[1][2]) * SC;
                    float* b1 = base + 16 + 6 * c;
                    asm volatile("red.global.add.v2.f32 [%0], {%1, %2};"
                                 :: "l"(b1), "f"(o0), "f"(o1) : "memory");
                    asm volatile("red.global.add.v2.f32 [%0], {%1, %2};"
                                 :: "l"(b1 + 2), "f"(o2), "f"(o3) : "memory");
                    asm volatile("red.global.add.v2.f32 [%0], {%1, %2};"
                                 :: "l"(b1 + 4), "f"(o4), "f"(o5) : "memory");
                }
            }
        }
        __syncthreads();
    }
}

extern "C" void kernel_launch(void* const* d_in, const int* in_sizes, int n_in,
                              void* d_out, int out_size) {
    const float* pos  = (const float*)d_in[0];
    const float* f_in = (const float*)d_in[1];
    const int*   esrc = (const int*)d_in[2];
    const int*   edst = (const int*)d_in[3];
    const float* W1   = (const float*)d_in[4];
    const float* W2   = (const float*)d_in[5];
    float* out = (float*)d_out;
    int n_edges = in_sizes[2];

    cudaFuncSetAttribute(conv_kernel, cudaFuncAttributeMaxDynamicSharedMemorySize, SMEM_TOTAL);

    int n4 = out_size / 4;
    zero_kernel<<<(n4 + 255) / 256, 256>>>((float4*)out, n4);
    conv_kernel<<<GRID, THREADS, SMEM_TOTAL>>>(pos, f_in, esrc, edst, W1, W2, out, n_edges);
}